// round 14
// baseline (speedup 1.0000x reference)
#include <cuda_runtime.h>
#include <cstdint>
#include <math.h>

#define Nn 50000
#define Ee 400000
#define FNd 128
#define FEd 64
#define Hh 128
#define HEADS 4
#define Ll 3
#define Bb 16

#define YS_STR 516           // y-tile smem stride (floats): conflict-free A-frag reads
#define LN_STR 132           // LN staging stride
#define WFRAG_PER_L (64 * 16 * 32 * 4)   // kt x nt x lane x {b0hi,b1hi,b0lo,b1lo}

// ------------------- scratch (device globals; no allocs allowed) -------------------
__device__ float    g_xA[(Nn + 32) * Hh];
__device__ float    g_xB[(Nn + 32) * Hh];
__device__ float    g_alec[(size_t)Ll * Ee * HEADS]; // edge att logits, CSR order
__device__ float    g_ale_loop[Ll * HEADS];
__device__ float    g_aeproj[Ll * Hh * HEADS];       // Weg-folded att_edge
__device__ float    g_asproj[Ll * Hh * HEADS];
__device__ float    g_adproj[Ll * Hh * HEADS];
__device__ float    g_aep2[Ll * HEADS * FEd];        // Wep @ aeproj  (ef-space)
__device__ float    g_bconst[Ll * HEADS];            // bep . aeproj
__device__ float    g_efsum[FEd];
__device__ float    g_wfrag[Ll * WFRAG_PER_L];       // tf32 hi/lo fragment-ready W
__device__ float    g_alsA[Nn * HEADS];              // double-buffered (race-free fusion)
__device__ float    g_aldA[Nn * HEADS];
__device__ float    g_alsB[Nn * HEADS];
__device__ float    g_aldB[Nn * HEADS];
__device__ int      g_deg[Nn];
__device__ int      g_off[Nn];
__device__ int      g_rowptr[Nn + 1];
__device__ int      g_srcc[Ee];
__device__ int      g_pos[Ee];                       // edge -> CSR slot
__device__ float    g_pool[Bb * 4 * Hh];
__device__ float    g_cnt[Bb];

// ---- tf32 helpers ----
__device__ __forceinline__ uint32_t f2tf32(float x) {
    uint32_t r; asm("cvt.rna.tf32.f32 %0, %1;" : "=r"(r) : "f"(x)); return r;
}
__device__ __forceinline__ void mma_tf32(float* d, uint32_t a0, uint32_t a1,
                                         uint32_t a2, uint32_t a3,
                                         uint32_t b0, uint32_t b1) {
    asm("mma.sync.aligned.m16n8k8.row.col.f32.tf32.tf32.f32 "
        "{%0,%1,%2,%3},{%4,%5,%6,%7},{%8,%9},{%0,%1,%2,%3};"
        : "+f"(d[0]), "+f"(d[1]), "+f"(d[2]), "+f"(d[3])
        : "r"(a0), "r"(a1), "r"(a2), "r"(a3), "r"(b0), "r"(b1));
}

// ------------------- K0: fold att vectors into W -------------------
__global__ void k_proj_tables(const float* __restrict__ Wg, const float* __restrict__ Weg,
                              const float* __restrict__ as_, const float* __restrict__ ad_,
                              const float* __restrict__ ae_) {
    int idx = blockIdx.x * blockDim.x + threadIdx.x;
    const int per = Ll * Hh * HEADS;
    if (idx >= 3 * per) return;
    int mat = idx / per;
    int r = idx % per;
    int l = r / (Hh * HEADS);
    int k = (r / HEADS) % Hh;
    int h = r % HEADS;
    const float* W   = (mat == 0) ? Weg : Wg;
    const float* att = (mat == 0) ? ae_ : (mat == 1 ? as_ : ad_);
    const float* wrow = W + ((size_t)l * Hh + k) * (HEADS * Hh) + h * Hh;
    const float* arow = att + ((size_t)l * HEADS + h) * Hh;
    float acc = 0.f;
    #pragma unroll 4
    for (int c = 0; c < Hh; c++) acc += wrow[c] * arow[c];
    float* dst = (mat == 0) ? g_aeproj : (mat == 1 ? g_asproj : g_adproj);
    dst[l * Hh * HEADS + k * HEADS + h] = acc;
}

// ------------------- K0b: aep2 = Wep @ aeproj; bconst = bep . aeproj ----
__global__ void k_aep2(const float* __restrict__ Wep, const float* __restrict__ bep) {
    int idx = blockIdx.x * blockDim.x + threadIdx.x;
    if (idx < Ll * HEADS * FEd) {
        int l = idx / (HEADS * FEd);
        int h = (idx / FEd) % HEADS;
        int k = idx % FEd;
        float acc = 0.f;
        #pragma unroll 4
        for (int c = 0; c < Hh; c++)
            acc += Wep[k * Hh + c] * g_aeproj[l * Hh * HEADS + c * HEADS + h];
        g_aep2[(l * HEADS + h) * FEd + k] = acc;
    } else if (idx < Ll * HEADS * FEd + Ll * HEADS) {
        int j = idx - Ll * HEADS * FEd;
        int l = j / HEADS, h = j % HEADS;
        float acc = 0.f;
        for (int c = 0; c < Hh; c++)
            acc += bep[c] * g_aeproj[l * Hh * HEADS + c * HEADS + h];
        g_bconst[j] = acc;
    }
}

// ------------------- K0c: W_gat -> fragment-ready tf32 hi/lo layout ---------------
__global__ void k_wfrag(const float* __restrict__ Wg) {
    int idx = blockIdx.x * blockDim.x + threadIdx.x;
    if (idx >= Ll * 64 * 16 * 32) return;
    int l = idx / 32768;
    int rem = idx % 32768;
    int kt = rem / 512;
    int nt = (rem / 32) % 16;
    int lane = rem % 32;
    int k0 = kt * 8 + (lane & 3);
    int k1 = k0 + 4;
    int n = nt * 8 + (lane >> 2);
    float w0 = Wg[((size_t)l * 128 + (k0 & 127)) * 512 + (k0 >> 7) * 128 + n];
    float w1 = Wg[((size_t)l * 128 + (k1 & 127)) * 512 + (k1 >> 7) * 128 + n];
    float h0 = __uint_as_float(f2tf32(w0));
    float h1 = __uint_as_float(f2tf32(w1));
    float* o = g_wfrag + (size_t)l * WFRAG_PER_L + (size_t)(rem) * 4;
    o[0] = h0; o[1] = h1; o[2] = w0 - h0; o[3] = w1 - h1;
}

// ------------------- K0d: zero the padded tail rows of both x buffers -------------
__global__ void k_padzero() {
    int i = blockIdx.x * blockDim.x + threadIdx.x;
    if (i < 32 * Hh) {
        g_xA[(size_t)Nn * Hh + i] = 0.f;
        g_xB[(size_t)Nn * Hh + i] = 0.f;
    }
}

// ------------------- CSR build -------------------
__global__ void k_hist(const int* __restrict__ ei) {
    int e = blockIdx.x * blockDim.x + threadIdx.x;
    if (e < Ee) atomicAdd(&g_deg[ei[Ee + e]], 1);
}

// coalesced pass-based scan: 1024 threads, warp-shuffle intra-pass
__global__ void __launch_bounds__(1024) k_scan() {
    __shared__ int wsum[32];
    __shared__ int carry;
    int t = threadIdx.x;
    int lane = t & 31, wid = t >> 5;
    if (t == 0) carry = 0;
    __syncthreads();
    const int NP = (Nn + 1023) / 1024;   // 49
    for (int p = 0; p < NP; p++) {
        int i = p * 1024 + t;
        int v = (i < Nn) ? g_deg[i] : 0;
        int incl = v;
        #pragma unroll
        for (int off = 1; off < 32; off <<= 1) {
            int u = __shfl_up_sync(0xffffffffu, incl, off);
            if (lane >= off) incl += u;
        }
        if (lane == 31) wsum[wid] = incl;
        __syncthreads();
        if (wid == 0) {
            int w = wsum[lane];
            int wi = w;
            #pragma unroll
            for (int off = 1; off < 32; off <<= 1) {
                int u = __shfl_up_sync(0xffffffffu, wi, off);
                if (lane >= off) wi += u;
            }
            wsum[lane] = wi - w;   // exclusive
        }
        __syncthreads();
        int base = carry + wsum[wid];
        if (i < Nn) g_rowptr[i] = base + incl - v;
        __syncthreads();           // all carry/wsum reads done before update
        if (t == 1023) carry += wsum[31] + incl;
        __syncthreads();
    }
    if (t == 1023) g_rowptr[Nn] = carry;
}

__global__ void k_fill(const int* __restrict__ ei) {
    int e = blockIdx.x * blockDim.x + threadIdx.x;
    if (e >= Ee) return;
    int src = ei[e], dst = ei[Ee + e];
    int pos = g_rowptr[dst] + atomicAdd(&g_off[dst], 1);
    g_srcc[pos] = src;
    g_pos[e]   = pos;
}

// ------------------- K1: x = nf @ W_proj + b + type_table[types], 16 rows ---------
__global__ void k_nodeproj(const float* __restrict__ nf, const float* __restrict__ Wp,
                           const float* __restrict__ bp, const float* __restrict__ tt,
                           const int* __restrict__ types) {
    __shared__ __align__(16) float xs[16 * FNd];
    int n0 = blockIdx.x * 16, tid = threadIdx.x; // 128 threads
    for (int i = tid; i < 16 * FNd; i += 128) xs[i] = nf[(size_t)n0 * FNd + i];
    __syncthreads();
    float acc[16];
    #pragma unroll
    for (int m = 0; m < 16; m++) acc[m] = 0.f;
    for (int k = 0; k < FNd; k += 4) {
        float b0 = Wp[(k + 0) * Hh + tid], b1 = Wp[(k + 1) * Hh + tid];
        float b2 = Wp[(k + 2) * Hh + tid], b3 = Wp[(k + 3) * Hh + tid];
        #pragma unroll
        for (int m = 0; m < 16; m++) {
            float4 a = ((const float4*)xs)[m * (FNd / 4) + (k >> 2)];
            acc[m] += a.x * b0 + a.y * b1 + a.z * b2 + a.w * b3;
        }
    }
    float bj = bp[tid];
    for (int m = 0; m < 16; m++) {
        int n = n0 + m;
        g_xA[(size_t)n * Hh + tid] = acc[m] + bj + tt[(size_t)types[n] * Hh + tid];
    }
}

// ------------------- K2: column sum of ef -------------------
__global__ void k_efsum(const float* __restrict__ ef) {
    __shared__ float sm[256];
    int c = threadIdx.x & 63, r = threadIdx.x >> 6;
    float acc = 0.f;
    for (int row = blockIdx.x * 4 + r; row < Ee; row += gridDim.x * 4)
        acc += ef[(size_t)row * FEd + c];
    sm[threadIdx.x] = acc;
    __syncthreads();
    if (threadIdx.x < 64) {
        float s = sm[c] + sm[64 + c] + sm[128 + c] + sm[192 + c];
        atomicAdd(&g_efsum[c], s);
    }
}

// ------------------- K3: self-loop al_e from ef column-mean -------------------
__global__ void k_loop_ale2() {
    int j = threadIdx.x;
    if (j < Ll * HEADS) {
        float acc = g_bconst[j];
        for (int k = 0; k < FEd; k++)
            acc += (g_efsum[k] * (1.0f / Ee)) * g_aep2[j * FEd + k];
        g_ale_loop[j] = acc;
    }
}

// ------------------- K4: edge logits in EDGE order (coalesced ef), scatter via pos ----
__global__ void k_ale_eorder(const float* __restrict__ ef) {
    int e = blockIdx.x * 8 + (threadIdx.x >> 5);
    if (e >= Ee) return;
    int lane = threadIdx.x & 31;
    float2 v = ((const float2*)ef)[(size_t)e * 32 + lane];
    int pos = g_pos[e];
    #pragma unroll
    for (int l = 0; l < Ll; l++) {
        float out[4];
        #pragma unroll
        for (int h = 0; h < 4; h++) {
            const float* a = g_aep2 + (l * 4 + h) * FEd;
            float acc = v.x * a[2 * lane] + v.y * a[2 * lane + 1];
            #pragma unroll
            for (int o = 16; o > 0; o >>= 1) acc += __shfl_xor_sync(0xffffffffu, acc, o);
            out[h] = acc + g_bconst[l * 4 + h];
        }
        if (lane == 0)
            ((float4*)g_alec)[(size_t)l * Ee + pos] =
                make_float4(out[0], out[1], out[2], out[3]);
    }
}

// ------------------- K5: al_src/al_dst, warp per node (layer 0 only) -------------
__global__ void k_att_sd(int layer, const float* __restrict__ x,
                         float* __restrict__ als, float* __restrict__ ald) {
    int n = blockIdx.x * 8 + (threadIdx.x >> 5);
    if (n >= Nn) return;
    int lane = threadIdx.x & 31;
    const float* asp = g_asproj + layer * Hh * HEADS;
    const float* adp = g_adproj + layer * Hh * HEADS;
    float4 v = ((const float4*)x)[(size_t)n * 32 + lane];
    float vv[4] = {v.x, v.y, v.z, v.w};
    float ss[HEADS] = {0, 0, 0, 0}, dd[HEADS] = {0, 0, 0, 0};
    #pragma unroll
    for (int i = 0; i < 4; i++) {
        int k = lane * 4 + i;
        #pragma unroll
        for (int h = 0; h < HEADS; h++) {
            ss[h] += vv[i] * asp[k * HEADS + h];
            dd[h] += vv[i] * adp[k * HEADS + h];
        }
    }
    #pragma unroll
    for (int h = 0; h < HEADS; h++) {
        #pragma unroll
        for (int o = 16; o > 0; o >>= 1) {
            ss[h] += __shfl_xor_sync(0xffffffffu, ss[h], o);
            dd[h] += __shfl_xor_sync(0xffffffffu, dd[h], o);
        }
    }
    if (lane == 0) {
        #pragma unroll
        for (int h = 0; h < HEADS; h++) {
            als[n * HEADS + h] = ss[h];
            ald[n * HEADS + h] = dd[h];
        }
    }
}

// ------------------- K6: layer: aggregate -> smem y -> tf32 MMA -> LN -> GELU -----
// Phase-1 = R11's single-prefetch loop (low regs). Fused epilogue writes next
// layer's als/ald into the OTHER buffer (race-free), or pooling on last layer.
__device__ __forceinline__ void leaky_exp4(float a[4]) {
    #pragma unroll
    for (int h = 0; h < 4; h++) {
        float t = (a[h] > 0.f) ? a[h] : 0.2f * a[h];
        a[h] = __expf(t);
    }
}

__global__ void __launch_bounds__(256) k_layer(int layer,
                                               const float* __restrict__ xin,
                                               float* __restrict__ xout,
                                               const float* __restrict__ als,
                                               const float* __restrict__ ald,
                                               float* __restrict__ alsN,
                                               float* __restrict__ aldN,
                                               const float* __restrict__ bias,
                                               const float* __restrict__ lg,
                                               const float* __restrict__ lb,
                                               const int* __restrict__ batch,
                                               const int* __restrict__ types,
                                               float* __restrict__ dout, int last) {
    extern __shared__ __align__(16) float ys[];   // 32*516 floats = 66048 B
    int n0 = blockIdx.x * 32;
    int tid = threadIdx.x, wid = tid >> 5, lane = tid & 31;

    const float4* x4 = (const float4*)xin;
    const float4* als4 = (const float4*)als;
    const float4* alec = (const float4*)(g_alec + (size_t)layer * Ee * HEADS);
    float4 ael = *((const float4*)&g_ale_loop[layer * 4]);

    // ---- phase 1: aggregation (warp per node, 4 nodes per warp) ----
    for (int mm = 0; mm < 4; mm++) {
        int m = wid * 4 + mm;
        int n = n0 + m;
        if (n < Nn) {
            float4 ad  = ((const float4*)ald)[n];
            float4 as0 = als4[n];
            float p[4] = {as0.x + ad.x + ael.x, as0.y + ad.y + ael.y,
                          as0.z + ad.z + ael.z, as0.w + ad.w + ael.w};
            leaky_exp4(p);
            float z[4] = {p[0], p[1], p[2], p[3]};
            float4 xn = x4[(size_t)n * 32 + lane];
            float4 acc[4];
            #pragma unroll
            for (int h = 0; h < 4; h++)
                acc[h] = make_float4(p[h] * xn.x, p[h] * xn.y, p[h] * xn.z, p[h] * xn.w);

            int r0 = g_rowptr[n], r1 = g_rowptr[n + 1];
            int src_next = (r0 < r1) ? g_srcc[r0] : 0;
            for (int pos = r0; pos < r1; pos++) {
                int src = src_next;
                if (pos + 1 < r1) src_next = g_srcc[pos + 1];
                float4 ale = alec[pos];
                float4 s   = als4[src];
                float a[4] = {s.x + ad.x + ale.x, s.y + ad.y + ale.y,
                              s.z + ad.z + ale.z, s.w + ad.w + ale.w};
                leaky_exp4(a);
                #pragma unroll
                for (int h = 0; h < 4; h++) z[h] += a[h];
                float4 xv = x4[(size_t)src * 32 + lane];
                #pragma unroll
                for (int h = 0; h < 4; h++) {
                    acc[h].x += a[h] * xv.x; acc[h].y += a[h] * xv.y;
                    acc[h].z += a[h] * xv.z; acc[h].w += a[h] * xv.w;
                }
            }
            #pragma unroll
            for (int h = 0; h < 4; h++) {
                float w = __fdividef(0.25f, z[h] + 1e-16f);
                ((float4*)ys)[m * (YS_STR / 4) + h * 32 + lane] =
                    make_float4(acc[h].x * w, acc[h].y * w, acc[h].z * w, acc[h].w * w);
            }
        } else {
            #pragma unroll
            for (int h = 0; h < 4; h++)
                ((float4*)ys)[m * (YS_STR / 4) + h * 32 + lane] = make_float4(0.f, 0.f, 0.f, 0.f);
        }
    }
    __syncthreads();

    // ---- phase 2: D = y @ W2 via tf32 mma, 3-pass hi/lo split ----
    {
        int r = lane >> 2, c = lane & 3;
        int nt0 = wid * 2;
        const float4* wf = (const float4*)(g_wfrag + (size_t)layer * WFRAG_PER_L);
        float d[2][2][4];
        #pragma unroll
        for (int i = 0; i < 2; i++)
            #pragma unroll
            for (int j = 0; j < 2; j++)
                #pragma unroll
                for (int q = 0; q < 4; q++) d[i][j][q] = 0.f;

        for (int kt = 0; kt < 64; kt++) {
            float4 bA = wf[(kt * 16 + nt0) * 32 + lane];
            float4 bB = wf[(kt * 16 + nt0 + 1) * 32 + lane];
            uint32_t bAh0 = __float_as_uint(bA.x), bAh1 = __float_as_uint(bA.y);
            uint32_t bAl0 = __float_as_uint(bA.z), bAl1 = __float_as_uint(bA.w);
            uint32_t bBh0 = __float_as_uint(bB.x), bBh1 = __float_as_uint(bB.y);
            uint32_t bBl0 = __float_as_uint(bB.z), bBl1 = __float_as_uint(bB.w);
            #pragma unroll
            for (int mt = 0; mt < 2; mt++) {
                int base = (mt * 16 + r) * YS_STR + kt * 8 + c;
                float a0 = ys[base];
                float a1 = ys[base + 8 * YS_STR];
                float a2 = ys[base + 4];
                float a3 = ys[base + 8 * YS_STR + 4];
                uint32_t h0 = f2tf32(a0), h1 = f2tf32(a1), h2 = f2tf32(a2), h3 = f2tf32(a3);
                uint32_t l0 = __float_as_uint(a0 - __uint_as_float(h0));
                uint32_t l1 = __float_as_uint(a1 - __uint_as_float(h1));
                uint32_t l2 = __float_as_uint(a2 - __uint_as_float(h2));
                uint32_t l3 = __float_as_uint(a3 - __uint_as_float(h3));
                mma_tf32(d[mt][0], h0, h1, h2, h3, bAh0, bAh1);
                mma_tf32(d[mt][0], l0, l1, l2, l3, bAh0, bAh1);
                mma_tf32(d[mt][0], h0, h1, h2, h3, bAl0, bAl1);
                mma_tf32(d[mt][1], h0, h1, h2, h3, bBh0, bBh1);
                mma_tf32(d[mt][1], l0, l1, l2, l3, bBh0, bBh1);
                mma_tf32(d[mt][1], h0, h1, h2, h3, bBl0, bBl1);
            }
        }
        __syncthreads();

        // epilogue: + bias + residual; stage into ys with LN_STR
        #pragma unroll
        for (int mt = 0; mt < 2; mt++) {
            #pragma unroll
            for (int j = 0; j < 2; j++) {
                int col = (nt0 + j) * 8 + c * 2;
                int rl  = mt * 16 + r;
                int grow = n0 + rl;
                float bj0 = bias[col], bj1 = bias[col + 1];
                float v0 = d[mt][j][0] + bj0 + xin[(size_t)grow * Hh + col];
                float v1 = d[mt][j][1] + bj1 + xin[(size_t)grow * Hh + col + 1];
                float v2 = d[mt][j][2] + bj0 + xin[(size_t)(grow + 8) * Hh + col];
                float v3 = d[mt][j][3] + bj1 + xin[(size_t)(grow + 8) * Hh + col + 1];
                ys[rl * LN_STR + col]           = v0;
                ys[rl * LN_STR + col + 1]       = v1;
                ys[(rl + 8) * LN_STR + col]     = v2;
                ys[(rl + 8) * LN_STR + col + 1] = v3;
            }
        }
    }
    __syncthreads();

    // ---- phase 3: LN + GELU + fused next-layer att (other buffer) / pooling ----
    float4 gg = ((const float4*)lg)[lane];
    float4 bb = ((const float4*)lb)[lane];
    const float* aspN = g_asproj + (layer + 1 < Ll ? layer + 1 : 0) * Hh * HEADS;
    const float* adpN = g_adproj + (layer + 1 < Ll ? layer + 1 : 0) * Hh * HEADS;
    #pragma unroll
    for (int mm = 0; mm < 4; mm++) {
        int m = wid * 4 + mm;
        int row = n0 + m;
        float v[4] = {ys[m * LN_STR + lane * 4],     ys[m * LN_STR + lane * 4 + 1],
                      ys[m * LN_STR + lane * 4 + 2], ys[m * LN_STR + lane * 4 + 3]};
        float sum = v[0] + v[1] + v[2] + v[3];
        #pragma unroll
        for (int o = 16; o > 0; o >>= 1) sum += __shfl_xor_sync(0xffffffffu, sum, o);
        float mu = sum * (1.0f / Hh);
        float sq = 0.f;
        #pragma unroll
        for (int i = 0; i < 4; i++) { float t = v[i] - mu; sq += t * t; }
        #pragma unroll
        for (int o = 16; o > 0; o >>= 1) sq += __shfl_xor_sync(0xffffffffu, sq, o);
        float inv = rsqrtf(sq * (1.0f / Hh) + 1e-5f);
        float gv[4] = {gg.x, gg.y, gg.z, gg.w};
        float bv[4] = {bb.x, bb.y, bb.z, bb.w};
        #pragma unroll
        for (int i = 0; i < 4; i++) {
            float y = (v[i] - mu) * inv * gv[i] + bv[i];
            y = 0.5f * y * (1.0f + erff(y * 0.70710678118654752f));
            v[i] = y;
        }
        float4 ov = make_float4(v[0], v[1], v[2], v[3]);
        ((float4*)xout)[(size_t)row * 32 + lane] = ov;

        if (row < Nn) {
            if (!last) {
                float ss[4] = {0, 0, 0, 0}, dd2[4] = {0, 0, 0, 0};
                #pragma unroll
                for (int i = 0; i < 4; i++) {
                    int k = lane * 4 + i;
                    #pragma unroll
                    for (int h = 0; h < 4; h++) {
                        ss[h]  += v[i] * aspN[k * HEADS + h];
                        dd2[h] += v[i] * adpN[k * HEADS + h];
                    }
                }
                #pragma unroll
                for (int h = 0; h < 4; h++) {
                    #pragma unroll
                    for (int o = 16; o > 0; o >>= 1) {
                        ss[h]  += __shfl_xor_sync(0xffffffffu, ss[h], o);
                        dd2[h] += __shfl_xor_sync(0xffffffffu, dd2[h], o);
                    }
                }
                if (lane == 0) {
                    #pragma unroll
                    for (int h = 0; h < 4; h++) {
                        alsN[row * HEADS + h] = ss[h];
                        aldN[row * HEADS + h] = dd2[h];
                    }
                }
            } else {
                int b = batch[row];
                int t = types[row];
                int rg = (t <= 5) ? 0 : ((t <= 20) ? 1 : 2);
                if (lane == 0) atomicAdd(&g_cnt[b], 1.0f);
                #pragma unroll
                for (int i = 0; i < 4; i++) {
                    int c = lane * 4 + i;
                    atomicAdd(&g_pool[(b * 4 + rg) * Hh + c], v[i]);
                    atomicAdd(&g_pool[(b * 4 + 3) * Hh + c], v[i]);
                }
                ((float4*)dout)[(size_t)row * 32 + lane] = ov;
            }
        }
    }
}

// ------------------- K12: divide & write embedding -------------------
__global__ void k_emb(float* __restrict__ dout) {
    int idx = blockIdx.x * blockDim.x + threadIdx.x;
    if (idx >= Bb * 4 * Hh) return;
    int b = idx / (4 * Hh);
    float c = fmaxf(g_cnt[b], 1.0f);
    dout[(size_t)Nn * Hh + idx] = g_pool[idx] / c;
}

// ------------------- host -------------------
extern "C" void kernel_launch(void* const* d_in, const int* in_sizes, int n_in,
                              void* d_out, int out_size) {
    const float* nf   = (const float*)d_in[0];
    const float* ef   = (const float*)d_in[1];
    const int*   types= (const int*)d_in[2];
    const int*   ei   = (const int*)d_in[3];
    const int*   batch= (const int*)d_in[4];
    const float* Wp   = (const float*)d_in[5];
    const float* bp   = (const float*)d_in[6];
    const float* tt   = (const float*)d_in[7];
    const float* Wep  = (const float*)d_in[8];
    const float* bep  = (const float*)d_in[9];
    const float* Wg   = (const float*)d_in[10];
    const float* Weg  = (const float*)d_in[11];
    const float* as_  = (const float*)d_in[12];
    const float* ad_  = (const float*)d_in[13];
    const float* ae_  = (const float*)d_in[14];
    const float* gb   = (const float*)d_in[15];
    const float* lng  = (const float*)d_in[16];
    const float* lnb  = (const float*)d_in[17];
    float* dout = (float*)d_out;

    const int SMEM_LAYER = 32 * YS_STR * 4;   // 66048 B

    static int smem_set = 0;
    if (!smem_set) {
        cudaFuncSetAttribute(k_layer, cudaFuncAttributeMaxDynamicSharedMemorySize, SMEM_LAYER);
        smem_set = 1;
    }

    void *p_efsum, *p_deg, *p_off, *p_pool, *p_cnt, *p_xA, *p_xB;
    void *p_alsA, *p_aldA, *p_alsB, *p_aldB;
    cudaGetSymbolAddress(&p_efsum, g_efsum);
    cudaGetSymbolAddress(&p_deg,  g_deg);
    cudaGetSymbolAddress(&p_off,  g_off);
    cudaGetSymbolAddress(&p_pool, g_pool);
    cudaGetSymbolAddress(&p_cnt,  g_cnt);
    cudaGetSymbolAddress(&p_xA,   g_xA);
    cudaGetSymbolAddress(&p_xB,   g_xB);
    cudaGetSymbolAddress(&p_alsA, g_alsA);
    cudaGetSymbolAddress(&p_aldA, g_aldA);
    cudaGetSymbolAddress(&p_alsB, g_alsB);
    cudaGetSymbolAddress(&p_aldB, g_aldB);

    cudaMemsetAsync(p_efsum, 0, FEd * sizeof(float));
    cudaMemsetAsync(p_deg,  0, Nn * sizeof(int));
    cudaMemsetAsync(p_off,  0, Nn * sizeof(int));
    cudaMemsetAsync(p_pool, 0, Bb * 4 * Hh * sizeof(float));
    cudaMemsetAsync(p_cnt,  0, Bb * sizeof(float));

    k_padzero<<<(32 * Hh + 255) / 256, 256>>>();
    k_hist<<<(Ee + 255) / 256, 256>>>(ei);
    k_scan<<<1, 1024>>>();
    k_fill<<<(Ee + 255) / 256, 256>>>(ei);

    k_proj_tables<<<(3 * Ll * Hh * HEADS + 255) / 256, 256>>>(Wg, Weg, as_, ad_, ae_);
    k_aep2<<<(Ll * HEADS * FEd + Ll * HEADS + 127) / 128, 128>>>(Wep, bep);
    k_wfrag<<<(Ll * 64 * 16 * 32 + 255) / 256, 256>>>(Wg);
    k_nodeproj<<<Nn / 16, 128>>>(nf, Wp, bp, tt, types);
    k_efsum<<<512, 256>>>(ef);
    k_loop_ale2<<<1, 32>>>();
    k_ale_eorder<<<(Ee + 7) / 8, 256>>>(ef);

    float* xA = (float*)p_xA;
    float* xB = (float*)p_xB;
    float* alsBuf[2] = {(float*)p_alsA, (float*)p_alsB};
    float* aldBuf[2] = {(float*)p_aldA, (float*)p_aldB};

    k_att_sd<<<(Nn + 7) / 8, 256>>>(0, xA, alsBuf[0], aldBuf[0]);
    for (int l = 0; l < Ll; l++) {
        const float* xin = (l & 1) ? xB : xA;
        float* xout      = (l & 1) ? xA : xB;
        k_layer<<<(Nn + 31) / 32, 256, SMEM_LAYER>>>(
            l, xin, xout,
            alsBuf[l & 1], aldBuf[l & 1],
            alsBuf[(l + 1) & 1], aldBuf[(l + 1) & 1],
            gb + l * Hh, lng + l * Hh, lnb + l * Hh,
            batch, types,
            dout, l == Ll - 1);
    }

    k_emb<<<(Bb * 4 * Hh + 255) / 256, 256>>>(dout);
}

// round 16
// speedup vs baseline: 1.0852x; 1.0852x over previous
#include <cuda_runtime.h>
#include <cstdint>
#include <math.h>

#define Nn 50000
#define Ee 400000
#define FNd 128
#define FEd 64
#define Hh 128
#define HEADS 4
#define Ll 3
#define Bb 16

#define YS_STR 516           // y-tile smem stride (floats): conflict-free A-frag reads
#define LN_STR 132           // LN staging stride
#define WFRAG_PER_L (64 * 16 * 32 * 4)   // kt x nt x lane x {b0hi,b1hi,b0lo,b1lo}

// ------------------- scratch (device globals; no allocs allowed) -------------------
__device__ float    g_xA[(Nn + 32) * Hh];
__device__ float    g_xB[(Nn + 32) * Hh];
__device__ float    g_alec[(size_t)Ll * Ee * HEADS]; // edge att logits, CSR order
__device__ float    g_ale_loop[Ll * HEADS];
__device__ float    g_aeproj[Ll * Hh * HEADS];       // Weg-folded att_edge
__device__ float    g_asproj[Ll * Hh * HEADS];
__device__ float    g_adproj[Ll * Hh * HEADS];
__device__ float    g_aep2[Ll * HEADS * FEd];        // Wep @ aeproj  (ef-space)
__device__ float    g_bconst[Ll * HEADS];            // bep . aeproj
__device__ float    g_efsum[FEd];
__device__ float    g_wfrag[Ll * WFRAG_PER_L];       // tf32 hi/lo fragment-ready W
__device__ float    g_als[Nn * HEADS];
__device__ float    g_ald[Nn * HEADS];
__device__ int      g_deg[Nn];
__device__ int      g_off[Nn];
__device__ int      g_rowptr[Nn + 1];
__device__ int      g_srcc[Ee];
__device__ int      g_pos[Ee];                       // edge -> CSR slot
__device__ float    g_pool[Bb * 4 * Hh];
__device__ float    g_cnt[Bb];

// ---- tf32 helpers ----
__device__ __forceinline__ uint32_t f2tf32(float x) {
    uint32_t r; asm("cvt.rna.tf32.f32 %0, %1;" : "=r"(r) : "f"(x)); return r;
}
__device__ __forceinline__ void mma_tf32(float* d, uint32_t a0, uint32_t a1,
                                         uint32_t a2, uint32_t a3,
                                         uint32_t b0, uint32_t b1) {
    asm("mma.sync.aligned.m16n8k8.row.col.f32.tf32.tf32.f32 "
        "{%0,%1,%2,%3},{%4,%5,%6,%7},{%8,%9},{%0,%1,%2,%3};"
        : "+f"(d[0]), "+f"(d[1]), "+f"(d[2]), "+f"(d[3])
        : "r"(a0), "r"(a1), "r"(a2), "r"(a3), "r"(b0), "r"(b1));
}

// ------------------- K0: fold att vectors into W -------------------
__global__ void k_proj_tables(const float* __restrict__ Wg, const float* __restrict__ Weg,
                              const float* __restrict__ as_, const float* __restrict__ ad_,
                              const float* __restrict__ ae_) {
    int idx = blockIdx.x * blockDim.x + threadIdx.x;
    const int per = Ll * Hh * HEADS;
    if (idx >= 3 * per) return;
    int mat = idx / per;
    int r = idx % per;
    int l = r / (Hh * HEADS);
    int k = (r / HEADS) % Hh;
    int h = r % HEADS;
    const float* W   = (mat == 0) ? Weg : Wg;
    const float* att = (mat == 0) ? ae_ : (mat == 1 ? as_ : ad_);
    const float* wrow = W + ((size_t)l * Hh + k) * (HEADS * Hh) + h * Hh;
    const float* arow = att + ((size_t)l * HEADS + h) * Hh;
    float acc = 0.f;
    #pragma unroll 4
    for (int c = 0; c < Hh; c++) acc += wrow[c] * arow[c];
    float* dst = (mat == 0) ? g_aeproj : (mat == 1 ? g_asproj : g_adproj);
    dst[l * Hh * HEADS + k * HEADS + h] = acc;
}

// ------------------- K0b: aep2 = Wep @ aeproj; bconst = bep . aeproj ----
__global__ void k_aep2(const float* __restrict__ Wep, const float* __restrict__ bep) {
    int idx = blockIdx.x * blockDim.x + threadIdx.x;
    if (idx < Ll * HEADS * FEd) {
        int l = idx / (HEADS * FEd);
        int h = (idx / FEd) % HEADS;
        int k = idx % FEd;
        float acc = 0.f;
        #pragma unroll 4
        for (int c = 0; c < Hh; c++)
            acc += Wep[k * Hh + c] * g_aeproj[l * Hh * HEADS + c * HEADS + h];
        g_aep2[(l * HEADS + h) * FEd + k] = acc;
    } else if (idx < Ll * HEADS * FEd + Ll * HEADS) {
        int j = idx - Ll * HEADS * FEd;
        int l = j / HEADS, h = j % HEADS;
        float acc = 0.f;
        for (int c = 0; c < Hh; c++)
            acc += bep[c] * g_aeproj[l * Hh * HEADS + c * HEADS + h];
        g_bconst[j] = acc;
    }
}

// ------------------- K0c: W_gat -> fragment-ready tf32 hi/lo layout ---------------
__global__ void k_wfrag(const float* __restrict__ Wg) {
    int idx = blockIdx.x * blockDim.x + threadIdx.x;
    if (idx >= Ll * 64 * 16 * 32) return;
    int l = idx / 32768;
    int rem = idx % 32768;
    int kt = rem / 512;
    int nt = (rem / 32) % 16;
    int lane = rem % 32;
    int k0 = kt * 8 + (lane & 3);
    int k1 = k0 + 4;
    int n = nt * 8 + (lane >> 2);
    float w0 = Wg[((size_t)l * 128 + (k0 & 127)) * 512 + (k0 >> 7) * 128 + n];
    float w1 = Wg[((size_t)l * 128 + (k1 & 127)) * 512 + (k1 >> 7) * 128 + n];
    float h0 = __uint_as_float(f2tf32(w0));
    float h1 = __uint_as_float(f2tf32(w1));
    float* o = g_wfrag + (size_t)l * WFRAG_PER_L + (size_t)(rem) * 4;
    o[0] = h0; o[1] = h1; o[2] = w0 - h0; o[3] = w1 - h1;
}

// ------------------- K0d: zero the padded tail rows of both x buffers -------------
__global__ void k_padzero() {
    int i = blockIdx.x * blockDim.x + threadIdx.x;
    if (i < 32 * Hh) {
        g_xA[(size_t)Nn * Hh + i] = 0.f;
        g_xB[(size_t)Nn * Hh + i] = 0.f;
    }
}

// ------------------- CSR build -------------------
__global__ void k_hist(const int* __restrict__ ei) {
    int e = blockIdx.x * blockDim.x + threadIdx.x;
    if (e < Ee) atomicAdd(&g_deg[ei[Ee + e]], 1);
}

// coalesced pass-based scan: 1024 threads, warp-shuffle intra-pass
__global__ void __launch_bounds__(1024) k_scan() {
    __shared__ int wsum[32];
    __shared__ int carry;
    int t = threadIdx.x;
    int lane = t & 31, wid = t >> 5;
    if (t == 0) carry = 0;
    __syncthreads();
    const int NP = (Nn + 1023) / 1024;   // 49
    for (int p = 0; p < NP; p++) {
        int i = p * 1024 + t;
        int v = (i < Nn) ? g_deg[i] : 0;
        int incl = v;
        #pragma unroll
        for (int off = 1; off < 32; off <<= 1) {
            int u = __shfl_up_sync(0xffffffffu, incl, off);
            if (lane >= off) incl += u;
        }
        if (lane == 31) wsum[wid] = incl;
        __syncthreads();
        if (wid == 0) {
            int w = wsum[lane];
            int wi = w;
            #pragma unroll
            for (int off = 1; off < 32; off <<= 1) {
                int u = __shfl_up_sync(0xffffffffu, wi, off);
                if (lane >= off) wi += u;
            }
            wsum[lane] = wi - w;   // exclusive
        }
        __syncthreads();
        int base = carry + wsum[wid];
        if (i < Nn) g_rowptr[i] = base + incl - v;
        __syncthreads();           // all carry/wsum reads done before update
        if (t == 1023) carry += wsum[31] + incl;
        __syncthreads();
    }
    if (t == 1023) g_rowptr[Nn] = carry;
}

__global__ void k_fill(const int* __restrict__ ei) {
    int e = blockIdx.x * blockDim.x + threadIdx.x;
    if (e >= Ee) return;
    int src = ei[e], dst = ei[Ee + e];
    int pos = g_rowptr[dst] + atomicAdd(&g_off[dst], 1);
    g_srcc[pos] = src;
    g_pos[e]   = pos;
}

// ------------------- K1: x = nf @ W_proj + b + type_table[types], 16 rows ---------
__global__ void k_nodeproj(const float* __restrict__ nf, const float* __restrict__ Wp,
                           const float* __restrict__ bp, const float* __restrict__ tt,
                           const int* __restrict__ types) {
    __shared__ __align__(16) float xs[16 * FNd];
    int n0 = blockIdx.x * 16, tid = threadIdx.x; // 128 threads
    for (int i = tid; i < 16 * FNd; i += 128) xs[i] = nf[(size_t)n0 * FNd + i];
    __syncthreads();
    float acc[16];
    #pragma unroll
    for (int m = 0; m < 16; m++) acc[m] = 0.f;
    for (int k = 0; k < FNd; k += 4) {
        float b0 = Wp[(k + 0) * Hh + tid], b1 = Wp[(k + 1) * Hh + tid];
        float b2 = Wp[(k + 2) * Hh + tid], b3 = Wp[(k + 3) * Hh + tid];
        #pragma unroll
        for (int m = 0; m < 16; m++) {
            float4 a = ((const float4*)xs)[m * (FNd / 4) + (k >> 2)];
            acc[m] += a.x * b0 + a.y * b1 + a.z * b2 + a.w * b3;
        }
    }
    float bj = bp[tid];
    for (int m = 0; m < 16; m++) {
        int n = n0 + m;
        g_xA[(size_t)n * Hh + tid] = acc[m] + bj + tt[(size_t)types[n] * Hh + tid];
    }
}

// ------------------- K2: column sum of ef -------------------
__global__ void k_efsum(const float* __restrict__ ef) {
    __shared__ float sm[256];
    int c = threadIdx.x & 63, r = threadIdx.x >> 6;
    float acc = 0.f;
    for (int row = blockIdx.x * 4 + r; row < Ee; row += gridDim.x * 4)
        acc += ef[(size_t)row * FEd + c];
    sm[threadIdx.x] = acc;
    __syncthreads();
    if (threadIdx.x < 64) {
        float s = sm[c] + sm[64 + c] + sm[128 + c] + sm[192 + c];
        atomicAdd(&g_efsum[c], s);
    }
}

// ------------------- K3: self-loop al_e from ef column-mean -------------------
__global__ void k_loop_ale2() {
    int j = threadIdx.x;
    if (j < Ll * HEADS) {
        float acc = g_bconst[j];
        for (int k = 0; k < FEd; k++)
            acc += (g_efsum[k] * (1.0f / Ee)) * g_aep2[j * FEd + k];
        g_ale_loop[j] = acc;
    }
}

// ------------------- K4: edge logits in EDGE order (coalesced ef), scatter via pos ----
__global__ void k_ale_eorder(const float* __restrict__ ef) {
    int e = blockIdx.x * 8 + (threadIdx.x >> 5);
    if (e >= Ee) return;
    int lane = threadIdx.x & 31;
    float2 v = ((const float2*)ef)[(size_t)e * 32 + lane];
    int pos = g_pos[e];
    #pragma unroll
    for (int l = 0; l < Ll; l++) {
        float out[4];
        #pragma unroll
        for (int h = 0; h < 4; h++) {
            const float* a = g_aep2 + (l * 4 + h) * FEd;
            float acc = v.x * a[2 * lane] + v.y * a[2 * lane + 1];
            #pragma unroll
            for (int o = 16; o > 0; o >>= 1) acc += __shfl_xor_sync(0xffffffffu, acc, o);
            out[h] = acc + g_bconst[l * 4 + h];
        }
        if (lane == 0)
            ((float4*)g_alec)[(size_t)l * Ee + pos] =
                make_float4(out[0], out[1], out[2], out[3]);
    }
}

// ------------------- K5: al_src/al_dst, warp per node ----------------
__global__ void k_att_sd(int layer, const float* __restrict__ x) {
    int n = blockIdx.x * 8 + (threadIdx.x >> 5);
    if (n >= Nn) return;
    int lane = threadIdx.x & 31;
    const float* asp = g_asproj + layer * Hh * HEADS;
    const float* adp = g_adproj + layer * Hh * HEADS;
    float4 v = ((const float4*)x)[(size_t)n * 32 + lane];
    float vv[4] = {v.x, v.y, v.z, v.w};
    float ss[HEADS] = {0, 0, 0, 0}, dd[HEADS] = {0, 0, 0, 0};
    #pragma unroll
    for (int i = 0; i < 4; i++) {
        int k = lane * 4 + i;
        #pragma unroll
        for (int h = 0; h < HEADS; h++) {
            ss[h] += vv[i] * asp[k * HEADS + h];
            dd[h] += vv[i] * adp[k * HEADS + h];
        }
    }
    #pragma unroll
    for (int h = 0; h < HEADS; h++) {
        #pragma unroll
        for (int o = 16; o > 0; o >>= 1) {
            ss[h] += __shfl_xor_sync(0xffffffffu, ss[h], o);
            dd[h] += __shfl_xor_sync(0xffffffffu, dd[h], o);
        }
    }
    if (lane == 0) {
        #pragma unroll
        for (int h = 0; h < HEADS; h++) {
            g_als[n * HEADS + h] = ss[h];
            g_ald[n * HEADS + h] = dd[h];
        }
    }
}

// ------------------- K6: layer: aggregate -> smem y -> tf32 MMA GEMM -> LN -> GELU ----
__device__ __forceinline__ void leaky_exp4(float a[4]) {
    #pragma unroll
    for (int h = 0; h < 4; h++) {
        float t = (a[h] > 0.f) ? a[h] : 0.2f * a[h];
        a[h] = __expf(t);
    }
}

__global__ void __launch_bounds__(256) k_layer(int layer,
                                               const float* __restrict__ xin,
                                               float* __restrict__ xout,
                                               const float* __restrict__ bias,
                                               const float* __restrict__ lg,
                                               const float* __restrict__ lb,
                                               float* __restrict__ dout, int last) {
    extern __shared__ __align__(16) float ys[];   // 32*516 floats = 66048 B
    int n0 = blockIdx.x * 32;
    int tid = threadIdx.x, wid = tid >> 5, lane = tid & 31;

    const float4* x4 = (const float4*)xin;
    const float4* alec = (const float4*)(g_alec + (size_t)layer * Ee * HEADS);
    float4 ael = *((const float4*)&g_ale_loop[layer * 4]);

    // ---- phase 1: aggregation (warp per node, 4 nodes per warp) -> ys[m][0..511] ----
    for (int mm = 0; mm < 4; mm++) {
        int m = wid * 4 + mm;
        int n = n0 + m;
        if (n < Nn) {
            float4 ad  = ((const float4*)g_ald)[n];
            float4 as0 = ((const float4*)g_als)[n];
            float p[4] = {as0.x + ad.x + ael.x, as0.y + ad.y + ael.y,
                          as0.z + ad.z + ael.z, as0.w + ad.w + ael.w};
            leaky_exp4(p);
            float z[4] = {p[0], p[1], p[2], p[3]};
            float4 xn = x4[(size_t)n * 32 + lane];
            float4 acc[4];
            #pragma unroll
            for (int h = 0; h < 4; h++)
                acc[h] = make_float4(p[h] * xn.x, p[h] * xn.y, p[h] * xn.z, p[h] * xn.w);

            int r0 = g_rowptr[n], r1 = g_rowptr[n + 1];
            int src_next = (r0 < r1) ? g_srcc[r0] : 0;
            for (int pos = r0; pos < r1; pos++) {
                int src = src_next;
                if (pos + 1 < r1) src_next = g_srcc[pos + 1];
                float4 ale = alec[pos];
                float4 s   = ((const float4*)g_als)[src];
                float a[4] = {s.x + ad.x + ale.x, s.y + ad.y + ale.y,
                              s.z + ad.z + ale.z, s.w + ad.w + ale.w};
                leaky_exp4(a);
                #pragma unroll
                for (int h = 0; h < 4; h++) z[h] += a[h];
                float4 xv = x4[(size_t)src * 32 + lane];
                #pragma unroll
                for (int h = 0; h < 4; h++) {
                    acc[h].x += a[h] * xv.x; acc[h].y += a[h] * xv.y;
                    acc[h].z += a[h] * xv.z; acc[h].w += a[h] * xv.w;
                }
            }
            #pragma unroll
            for (int h = 0; h < 4; h++) {
                float w = __fdividef(0.25f, z[h] + 1e-16f);
                ((float4*)ys)[m * (YS_STR / 4) + h * 32 + lane] =
                    make_float4(acc[h].x * w, acc[h].y * w, acc[h].z * w, acc[h].w * w);
            }
        } else {
            #pragma unroll
            for (int h = 0; h < 4; h++)
                ((float4*)ys)[m * (YS_STR / 4) + h * 32 + lane] = make_float4(0.f, 0.f, 0.f, 0.f);
        }
    }
    __syncthreads();

    // ---- phase 2: D = y @ W2 via tf32 mma, 3-pass hi/lo split ----
    {
        int r = lane >> 2, c = lane & 3;
        int nt0 = wid * 2;
        const float4* wf = (const float4*)(g_wfrag + (size_t)layer * WFRAG_PER_L);
        float d[2][2][4];
        #pragma unroll
        for (int i = 0; i < 2; i++)
            #pragma unroll
            for (int j = 0; j < 2; j++)
                #pragma unroll
                for (int q = 0; q < 4; q++) d[i][j][q] = 0.f;

        for (int kt = 0; kt < 64; kt++) {
            float4 bA = wf[(kt * 16 + nt0) * 32 + lane];
            float4 bB = wf[(kt * 16 + nt0 + 1) * 32 + lane];
            uint32_t bAh0 = __float_as_uint(bA.x), bAh1 = __float_as_uint(bA.y);
            uint32_t bAl0 = __float_as_uint(bA.z), bAl1 = __float_as_uint(bA.w);
            uint32_t bBh0 = __float_as_uint(bB.x), bBh1 = __float_as_uint(bB.y);
            uint32_t bBl0 = __float_as_uint(bB.z), bBl1 = __float_as_uint(bB.w);
            #pragma unroll
            for (int mt = 0; mt < 2; mt++) {
                int base = (mt * 16 + r) * YS_STR + kt * 8 + c;
                float a0 = ys[base];
                float a1 = ys[base + 8 * YS_STR];
                float a2 = ys[base + 4];
                float a3 = ys[base + 8 * YS_STR + 4];
                uint32_t h0 = f2tf32(a0), h1 = f2tf32(a1), h2 = f2tf32(a2), h3 = f2tf32(a3);
                uint32_t l0 = __float_as_uint(a0 - __uint_as_float(h0));
                uint32_t l1 = __float_as_uint(a1 - __uint_as_float(h1));
                uint32_t l2 = __float_as_uint(a2 - __uint_as_float(h2));
                uint32_t l3 = __float_as_uint(a3 - __uint_as_float(h3));
                mma_tf32(d[mt][0], h0, h1, h2, h3, bAh0, bAh1);
                mma_tf32(d[mt][0], l0, l1, l2, l3, bAh0, bAh1);
                mma_tf32(d[mt][0], h0, h1, h2, h3, bAl0, bAl1);
                mma_tf32(d[mt][1], h0, h1, h2, h3, bBh0, bBh1);
                mma_tf32(d[mt][1], l0, l1, l2, l3, bBh0, bBh1);
                mma_tf32(d[mt][1], h0, h1, h2, h3, bBl0, bBl1);
            }
        }
        __syncthreads();   // all warps done reading ys; safe to overwrite as LN buffer

        // epilogue: + bias + residual; stage into ys with LN_STR
        #pragma unroll
        for (int mt = 0; mt < 2; mt++) {
            #pragma unroll
            for (int j = 0; j < 2; j++) {
                int col = (nt0 + j) * 8 + c * 2;
                int rl  = mt * 16 + r;
                int grow = n0 + rl;
                float bj0 = bias[col], bj1 = bias[col + 1];
                float v0 = d[mt][j][0] + bj0 + xin[(size_t)grow * Hh + col];
                float v1 = d[mt][j][1] + bj1 + xin[(size_t)grow * Hh + col + 1];
                float v2 = d[mt][j][2] + bj0 + xin[(size_t)(grow + 8) * Hh + col];
                float v3 = d[mt][j][3] + bj1 + xin[(size_t)(grow + 8) * Hh + col + 1];
                ys[rl * LN_STR + col]           = v0;
                ys[rl * LN_STR + col + 1]       = v1;
                ys[(rl + 8) * LN_STR + col]     = v2;
                ys[(rl + 8) * LN_STR + col + 1] = v3;
            }
        }
    }
    __syncthreads();

    // ---- phase 3: LN + GELU, 8 warps x 4 rows ----
    float4 gg = ((const float4*)lg)[lane];
    float4 bb = ((const float4*)lb)[lane];
    #pragma unroll
    for (int mm = 0; mm < 4; mm++) {
        int m = wid * 4 + mm;
        int row = n0 + m;
        float v[4] = {ys[m * LN_STR + lane * 4],     ys[m * LN_STR + lane * 4 + 1],
                      ys[m * LN_STR + lane * 4 + 2], ys[m * LN_STR + lane * 4 + 3]};
        float sum = v[0] + v[1] + v[2] + v[3];
        #pragma unroll
        for (int o = 16; o > 0; o >>= 1) sum += __shfl_xor_sync(0xffffffffu, sum, o);
        float mu = sum * (1.0f / Hh);
        float sq = 0.f;
        #pragma unroll
        for (int i = 0; i < 4; i++) { float t = v[i] - mu; sq += t * t; }
        #pragma unroll
        for (int o = 16; o > 0; o >>= 1) sq += __shfl_xor_sync(0xffffffffu, sq, o);
        float inv = rsqrtf(sq * (1.0f / Hh) + 1e-5f);
        float gv[4] = {gg.x, gg.y, gg.z, gg.w};
        float bv[4] = {bb.x, bb.y, bb.z, bb.w};
        #pragma unroll
        for (int i = 0; i < 4; i++) {
            float y = (v[i] - mu) * inv * gv[i] + bv[i];
            y = 0.5f * y * (1.0f + erff(y * 0.70710678118654752f));
            v[i] = y;
        }
        float4 ov = make_float4(v[0], v[1], v[2], v[3]);
        ((float4*)xout)[(size_t)row * 32 + lane] = ov;
        if (last && row < Nn) ((float4*)dout)[(size_t)row * 32 + lane] = ov;
    }
}

// ------------------- K11: pooling atomics -------------------
__global__ void k_pool(const float* __restrict__ x,
                       const int* __restrict__ batch, const int* __restrict__ types) {
    int n = blockIdx.x * 8 + (threadIdx.x >> 5);
    if (n >= Nn) return;
    int lane = threadIdx.x & 31;
    int b = batch[n];
    int t = types[n];
    int r = (t <= 5) ? 0 : ((t <= 20) ? 1 : 2);
    if (lane == 0) atomicAdd(&g_cnt[b], 1.0f);
    #pragma unroll
    for (int i = 0; i < 4; i++) {
        int c = lane + 32 * i;
        float v = x[(size_t)n * Hh + c];
        atomicAdd(&g_pool[(b * 4 + r) * Hh + c], v);
        atomicAdd(&g_pool[(b * 4 + 3) * Hh + c], v);
    }
}

// ------------------- K12: divide & write embedding -------------------
__global__ void k_emb(float* __restrict__ dout) {
    int idx = blockIdx.x * blockDim.x + threadIdx.x;
    if (idx >= Bb * 4 * Hh) return;
    int b = idx / (4 * Hh);
    float c = fmaxf(g_cnt[b], 1.0f);
    dout[(size_t)Nn * Hh + idx] = g_pool[idx] / c;
}

// ------------------- host -------------------
extern "C" void kernel_launch(void* const* d_in, const int* in_sizes, int n_in,
                              void* d_out, int out_size) {
    const float* nf   = (const float*)d_in[0];
    const float* ef   = (const float*)d_in[1];
    const int*   types= (const int*)d_in[2];
    const int*   ei   = (const int*)d_in[3];
    const int*   batch= (const int*)d_in[4];
    const float* Wp   = (const float*)d_in[5];
    const float* bp   = (const float*)d_in[6];
    const float* tt   = (const float*)d_in[7];
    const float* Wep  = (const float*)d_in[8];
    const float* bep  = (const float*)d_in[9];
    const float* Wg   = (const float*)d_in[10];
    const float* Weg  = (const float*)d_in[11];
    const float* as_  = (const float*)d_in[12];
    const float* ad_  = (const float*)d_in[13];
    const float* ae_  = (const float*)d_in[14];
    const float* gb   = (const float*)d_in[15];
    const float* lng  = (const float*)d_in[16];
    const float* lnb  = (const float*)d_in[17];
    float* dout = (float*)d_out;

    const int SMEM_LAYER = 32 * YS_STR * 4;   // 66048 B

    static int smem_set = 0;
    if (!smem_set) {
        cudaFuncSetAttribute(k_layer, cudaFuncAttributeMaxDynamicSharedMemorySize, SMEM_LAYER);
        smem_set = 1;
    }

    void *p_efsum, *p_deg, *p_off, *p_pool, *p_cnt, *p_xA, *p_xB;
    cudaGetSymbolAddress(&p_efsum, g_efsum);
    cudaGetSymbolAddress(&p_deg,  g_deg);
    cudaGetSymbolAddress(&p_off,  g_off);
    cudaGetSymbolAddress(&p_pool, g_pool);
    cudaGetSymbolAddress(&p_cnt,  g_cnt);
    cudaGetSymbolAddress(&p_xA,   g_xA);
    cudaGetSymbolAddress(&p_xB,   g_xB);

    cudaMemsetAsync(p_efsum, 0, FEd * sizeof(float));
    cudaMemsetAsync(p_deg,  0, Nn * sizeof(int));
    cudaMemsetAsync(p_off,  0, Nn * sizeof(int));

    k_padzero<<<(32 * Hh + 255) / 256, 256>>>();
    k_hist<<<(Ee + 255) / 256, 256>>>(ei);
    k_scan<<<1, 1024>>>();
    k_fill<<<(Ee + 255) / 256, 256>>>(ei);

    k_proj_tables<<<(3 * Ll * Hh * HEADS + 255) / 256, 256>>>(Wg, Weg, as_, ad_, ae_);
    k_aep2<<<(Ll * HEADS * FEd + Ll * HEADS + 127) / 128, 128>>>(Wep, bep);
    k_wfrag<<<(Ll * 64 * 16 * 32 + 255) / 256, 256>>>(Wg);
    k_nodeproj<<<Nn / 16, 128>>>(nf, Wp, bp, tt, types);
    k_efsum<<<512, 256>>>(ef);
    k_loop_ale2<<<1, 32>>>();
    k_ale_eorder<<<(Ee + 7) / 8, 256>>>(ef);

    float* xA = (float*)p_xA;
    float* xB = (float*)p_xB;
    for (int l = 0; l < Ll; l++) {
        const float* xin = (l & 1) ? xB : xA;
        float* xout      = (l & 1) ? xA : xB;
        k_att_sd<<<(Nn + 7) / 8, 256>>>(l, xin);
        k_layer<<<(Nn + 31) / 32, 256, SMEM_LAYER>>>(l, xin, xout,
                                                     gb + l * Hh, lng + l * Hh, lnb + l * Hh,
                                                     dout, l == Ll - 1);
    }

    const float* xfinal = (Ll & 1) ? xB : xA;   // L=3 -> final in xB
    cudaMemsetAsync(p_pool, 0, Bb * 4 * Hh * sizeof(float));
    cudaMemsetAsync(p_cnt,  0, Bb * sizeof(float));
    k_pool<<<(Nn + 7) / 8, 256>>>(xfinal, batch, types);
    k_emb<<<(Bb * 4 * Hh + 255) / 256, 256>>>(dout);
}

// round 17
// speedup vs baseline: 1.1053x; 1.0185x over previous
#include <cuda_runtime.h>
#include <cstdint>
#include <math.h>

#define Nn 50000
#define Ee 400000
#define FNd 128
#define FEd 64
#define Hh 128
#define HEADS 4
#define Ll 3
#define Bb 16

#define YS_STR 516           // y-tile smem stride (floats): conflict-free A-frag reads
#define LN_STR 132           // LN staging stride
#define WFRAG_PER_L (64 * 16 * 32 * 4)   // kt x nt x lane x {b0hi,b1hi,b0lo,b1lo}

// ------------------- scratch (device globals; no allocs allowed) -------------------
__device__ float    g_xA[(Nn + 32) * Hh];
__device__ float    g_xB[(Nn + 32) * Hh];
__device__ float    g_alec[(size_t)Ll * Ee * HEADS]; // edge att logits, CSR order
__device__ float    g_ale_loop[Ll * HEADS];
__device__ float    g_aeproj[Ll * Hh * HEADS];       // Weg-folded att_edge
__device__ float    g_asproj[Ll * Hh * HEADS];
__device__ float    g_adproj[Ll * Hh * HEADS];
__device__ float    g_aep2[Ll * HEADS * FEd];        // Wep @ aeproj  (ef-space)
__device__ float    g_bconst[Ll * HEADS];            // bep . aeproj
__device__ float    g_efsum[FEd];
__device__ float    g_wfrag[Ll * WFRAG_PER_L];       // tf32 hi/lo fragment-ready W
__device__ float    g_als[Nn * HEADS];
__device__ float    g_ald[Nn * HEADS];
__device__ int      g_deg[Nn];
__device__ int      g_off[Nn];
__device__ int      g_rowptr[Nn + 1];
__device__ int      g_srcc[Ee];
__device__ int      g_pos[Ee];                       // edge -> CSR slot
__device__ float    g_pool[Bb * 4 * Hh];
__device__ float    g_cnt[Bb];

// ---- tf32 helpers ----
__device__ __forceinline__ uint32_t f2tf32(float x) {
    uint32_t r; asm("cvt.rna.tf32.f32 %0, %1;" : "=r"(r) : "f"(x)); return r;
}
__device__ __forceinline__ void mma_tf32(float* d, uint32_t a0, uint32_t a1,
                                         uint32_t a2, uint32_t a3,
                                         uint32_t b0, uint32_t b1) {
    asm("mma.sync.aligned.m16n8k8.row.col.f32.tf32.tf32.f32 "
        "{%0,%1,%2,%3},{%4,%5,%6,%7},{%8,%9},{%0,%1,%2,%3};"
        : "+f"(d[0]), "+f"(d[1]), "+f"(d[2]), "+f"(d[3])
        : "r"(a0), "r"(a1), "r"(a2), "r"(a3), "r"(b0), "r"(b1));
}

// ------------------- K0: fold att vectors into W -------------------
__global__ void k_proj_tables(const float* __restrict__ Wg, const float* __restrict__ Weg,
                              const float* __restrict__ as_, const float* __restrict__ ad_,
                              const float* __restrict__ ae_) {
    int idx = blockIdx.x * blockDim.x + threadIdx.x;
    const int per = Ll * Hh * HEADS;
    if (idx >= 3 * per) return;
    int mat = idx / per;
    int r = idx % per;
    int l = r / (Hh * HEADS);
    int k = (r / HEADS) % Hh;
    int h = r % HEADS;
    const float* W   = (mat == 0) ? Weg : Wg;
    const float* att = (mat == 0) ? ae_ : (mat == 1 ? as_ : ad_);
    const float* wrow = W + ((size_t)l * Hh + k) * (HEADS * Hh) + h * Hh;
    const float* arow = att + ((size_t)l * HEADS + h) * Hh;
    float acc = 0.f;
    #pragma unroll 4
    for (int c = 0; c < Hh; c++) acc += wrow[c] * arow[c];
    float* dst = (mat == 0) ? g_aeproj : (mat == 1 ? g_asproj : g_adproj);
    dst[l * Hh * HEADS + k * HEADS + h] = acc;
}

// ------------------- K0b: aep2 = Wep @ aeproj; bconst = bep . aeproj ----
__global__ void k_aep2(const float* __restrict__ Wep, const float* __restrict__ bep) {
    int idx = blockIdx.x * blockDim.x + threadIdx.x;
    if (idx < Ll * HEADS * FEd) {
        int l = idx / (HEADS * FEd);
        int h = (idx / FEd) % HEADS;
        int k = idx % FEd;
        float acc = 0.f;
        #pragma unroll 4
        for (int c = 0; c < Hh; c++)
            acc += Wep[k * Hh + c] * g_aeproj[l * Hh * HEADS + c * HEADS + h];
        g_aep2[(l * HEADS + h) * FEd + k] = acc;
    } else if (idx < Ll * HEADS * FEd + Ll * HEADS) {
        int j = idx - Ll * HEADS * FEd;
        int l = j / HEADS, h = j % HEADS;
        float acc = 0.f;
        for (int c = 0; c < Hh; c++)
            acc += bep[c] * g_aeproj[l * Hh * HEADS + c * HEADS + h];
        g_bconst[j] = acc;
    }
}

// ------------------- K0c: W_gat -> fragment-ready tf32 hi/lo layout ---------------
__global__ void k_wfrag(const float* __restrict__ Wg) {
    int idx = blockIdx.x * blockDim.x + threadIdx.x;
    if (idx >= Ll * 64 * 16 * 32) return;
    int l = idx / 32768;
    int rem = idx % 32768;
    int kt = rem / 512;
    int nt = (rem / 32) % 16;
    int lane = rem % 32;
    int k0 = kt * 8 + (lane & 3);
    int k1 = k0 + 4;
    int n = nt * 8 + (lane >> 2);
    float w0 = Wg[((size_t)l * 128 + (k0 & 127)) * 512 + (k0 >> 7) * 128 + n];
    float w1 = Wg[((size_t)l * 128 + (k1 & 127)) * 512 + (k1 >> 7) * 128 + n];
    float h0 = __uint_as_float(f2tf32(w0));
    float h1 = __uint_as_float(f2tf32(w1));
    float* o = g_wfrag + (size_t)l * WFRAG_PER_L + (size_t)(rem) * 4;
    o[0] = h0; o[1] = h1; o[2] = w0 - h0; o[3] = w1 - h1;
}

// ------------------- K0d: zero the padded tail rows of both x buffers -------------
__global__ void k_padzero() {
    int i = blockIdx.x * blockDim.x + threadIdx.x;
    if (i < 32 * Hh) {
        g_xA[(size_t)Nn * Hh + i] = 0.f;
        g_xB[(size_t)Nn * Hh + i] = 0.f;
    }
}

// ------------------- CSR build -------------------
__global__ void k_hist(const int* __restrict__ ei) {
    int e = blockIdx.x * blockDim.x + threadIdx.x;
    if (e < Ee) atomicAdd(&g_deg[ei[Ee + e]], 1);
}

// coalesced pass-based scan: 1024 threads, warp-shuffle intra-pass
__global__ void __launch_bounds__(1024) k_scan() {
    __shared__ int wsum[32];
    __shared__ int carry;
    int t = threadIdx.x;
    int lane = t & 31, wid = t >> 5;
    if (t == 0) carry = 0;
    __syncthreads();
    const int NP = (Nn + 1023) / 1024;   // 49
    for (int p = 0; p < NP; p++) {
        int i = p * 1024 + t;
        int v = (i < Nn) ? g_deg[i] : 0;
        int incl = v;
        #pragma unroll
        for (int off = 1; off < 32; off <<= 1) {
            int u = __shfl_up_sync(0xffffffffu, incl, off);
            if (lane >= off) incl += u;
        }
        if (lane == 31) wsum[wid] = incl;
        __syncthreads();
        if (wid == 0) {
            int w = wsum[lane];
            int wi = w;
            #pragma unroll
            for (int off = 1; off < 32; off <<= 1) {
                int u = __shfl_up_sync(0xffffffffu, wi, off);
                if (lane >= off) wi += u;
            }
            wsum[lane] = wi - w;   // exclusive
        }
        __syncthreads();
        int base = carry + wsum[wid];
        if (i < Nn) g_rowptr[i] = base + incl - v;
        __syncthreads();           // all carry/wsum reads done before update
        if (t == 1023) carry += wsum[31] + incl;
        __syncthreads();
    }
    if (t == 1023) g_rowptr[Nn] = carry;
}

__global__ void k_fill(const int* __restrict__ ei) {
    int e = blockIdx.x * blockDim.x + threadIdx.x;
    if (e >= Ee) return;
    int src = ei[e], dst = ei[Ee + e];
    int pos = g_rowptr[dst] + atomicAdd(&g_off[dst], 1);
    g_srcc[pos] = src;
    g_pos[e]   = pos;
}

// ------------------- K1: x = nf @ W_proj + b + type_table[types], 16 rows ---------
__global__ void k_nodeproj(const float* __restrict__ nf, const float* __restrict__ Wp,
                           const float* __restrict__ bp, const float* __restrict__ tt,
                           const int* __restrict__ types) {
    __shared__ __align__(16) float xs[16 * FNd];
    int n0 = blockIdx.x * 16, tid = threadIdx.x; // 128 threads
    for (int i = tid; i < 16 * FNd; i += 128) xs[i] = nf[(size_t)n0 * FNd + i];
    __syncthreads();
    float acc[16];
    #pragma unroll
    for (int m = 0; m < 16; m++) acc[m] = 0.f;
    for (int k = 0; k < FNd; k += 4) {
        float b0 = Wp[(k + 0) * Hh + tid], b1 = Wp[(k + 1) * Hh + tid];
        float b2 = Wp[(k + 2) * Hh + tid], b3 = Wp[(k + 3) * Hh + tid];
        #pragma unroll
        for (int m = 0; m < 16; m++) {
            float4 a = ((const float4*)xs)[m * (FNd / 4) + (k >> 2)];
            acc[m] += a.x * b0 + a.y * b1 + a.z * b2 + a.w * b3;
        }
    }
    float bj = bp[tid];
    for (int m = 0; m < 16; m++) {
        int n = n0 + m;
        g_xA[(size_t)n * Hh + tid] = acc[m] + bj + tt[(size_t)types[n] * Hh + tid];
    }
}

// ------------------- K2: column sum of ef -------------------
__global__ void k_efsum(const float* __restrict__ ef) {
    __shared__ float sm[256];
    int c = threadIdx.x & 63, r = threadIdx.x >> 6;
    float acc = 0.f;
    for (int row = blockIdx.x * 4 + r; row < Ee; row += gridDim.x * 4)
        acc += ef[(size_t)row * FEd + c];
    sm[threadIdx.x] = acc;
    __syncthreads();
    if (threadIdx.x < 64) {
        float s = sm[c] + sm[64 + c] + sm[128 + c] + sm[192 + c];
        atomicAdd(&g_efsum[c], s);
    }
}

// ------------------- K3: self-loop al_e from ef column-mean -------------------
__global__ void k_loop_ale2() {
    int j = threadIdx.x;
    if (j < Ll * HEADS) {
        float acc = g_bconst[j];
        for (int k = 0; k < FEd; k++)
            acc += (g_efsum[k] * (1.0f / Ee)) * g_aep2[j * FEd + k];
        g_ale_loop[j] = acc;
    }
}

// ------------------- K4: edge logits in EDGE order (coalesced ef), scatter via pos ----
__global__ void k_ale_eorder(const float* __restrict__ ef) {
    int e = blockIdx.x * 8 + (threadIdx.x >> 5);
    if (e >= Ee) return;
    int lane = threadIdx.x & 31;
    float2 v = ((const float2*)ef)[(size_t)e * 32 + lane];
    int pos = g_pos[e];
    #pragma unroll
    for (int l = 0; l < Ll; l++) {
        float out[4];
        #pragma unroll
        for (int h = 0; h < 4; h++) {
            const float* a = g_aep2 + (l * 4 + h) * FEd;
            float acc = v.x * a[2 * lane] + v.y * a[2 * lane + 1];
            #pragma unroll
            for (int o = 16; o > 0; o >>= 1) acc += __shfl_xor_sync(0xffffffffu, acc, o);
            out[h] = acc + g_bconst[l * 4 + h];
        }
        if (lane == 0)
            ((float4*)g_alec)[(size_t)l * Ee + pos] =
                make_float4(out[0], out[1], out[2], out[3]);
    }
}

// ------------------- K5: al_src/al_dst, warp per node ----------------
__global__ void k_att_sd(int layer, const float* __restrict__ x) {
    int n = blockIdx.x * 8 + (threadIdx.x >> 5);
    if (n >= Nn) return;
    int lane = threadIdx.x & 31;
    const float* asp = g_asproj + layer * Hh * HEADS;
    const float* adp = g_adproj + layer * Hh * HEADS;
    float4 v = ((const float4*)x)[(size_t)n * 32 + lane];
    float vv[4] = {v.x, v.y, v.z, v.w};
    float ss[HEADS] = {0, 0, 0, 0}, dd[HEADS] = {0, 0, 0, 0};
    #pragma unroll
    for (int i = 0; i < 4; i++) {
        int k = lane * 4 + i;
        #pragma unroll
        for (int h = 0; h < HEADS; h++) {
            ss[h] += vv[i] * asp[k * HEADS + h];
            dd[h] += vv[i] * adp[k * HEADS + h];
        }
    }
    #pragma unroll
    for (int h = 0; h < HEADS; h++) {
        #pragma unroll
        for (int o = 16; o > 0; o >>= 1) {
            ss[h] += __shfl_xor_sync(0xffffffffu, ss[h], o);
            dd[h] += __shfl_xor_sync(0xffffffffu, dd[h], o);
        }
    }
    if (lane == 0) {
        #pragma unroll
        for (int h = 0; h < HEADS; h++) {
            g_als[n * HEADS + h] = ss[h];
            g_ald[n * HEADS + h] = dd[h];
        }
    }
}

// ------------------- K6: layer: aggregate -> smem y -> tf32 MMA GEMM -> LN -> GELU ----
__device__ __forceinline__ void leaky_exp4(float a[4]) {
    #pragma unroll
    for (int h = 0; h < 4; h++) {
        float t = (a[h] > 0.f) ? a[h] : 0.2f * a[h];
        a[h] = __expf(t);
    }
}

__global__ void __launch_bounds__(256) k_layer(int layer,
                                               const float* __restrict__ xin,
                                               float* __restrict__ xout,
                                               const float* __restrict__ bias,
                                               const float* __restrict__ lg,
                                               const float* __restrict__ lb,
                                               float* __restrict__ dout, int last) {
    extern __shared__ __align__(16) float ys[];   // 32*516 floats = 66048 B
    int n0 = blockIdx.x * 32;
    int tid = threadIdx.x, wid = tid >> 5, lane = tid & 31;

    const float4* x4 = (const float4*)xin;
    const float4* alec = (const float4*)(g_alec + (size_t)layer * Ee * HEADS);
    float4 ael = *((const float4*)&g_ale_loop[layer * 4]);

    // ---- phase 1: aggregation (warp per node, 4 nodes per warp), unroll-2 --------
    for (int mm = 0; mm < 4; mm++) {
        int m = wid * 4 + mm;
        int n = n0 + m;
        if (n < Nn) {
            float4 ad  = ((const float4*)g_ald)[n];
            float4 as0 = ((const float4*)g_als)[n];
            float p[4] = {as0.x + ad.x + ael.x, as0.y + ad.y + ael.y,
                          as0.z + ad.z + ael.z, as0.w + ad.w + ael.w};
            leaky_exp4(p);
            float z[4] = {p[0], p[1], p[2], p[3]};
            float4 xn = x4[(size_t)n * 32 + lane];
            float4 acc[4];
            #pragma unroll
            for (int h = 0; h < 4; h++)
                acc[h] = make_float4(p[h] * xn.x, p[h] * xn.y, p[h] * xn.z, p[h] * xn.w);

            int r0 = g_rowptr[n], r1 = g_rowptr[n + 1];
            int pos = r0;
            int sA = (pos < r1) ? g_srcc[pos] : 0;
            int sB = (pos + 1 < r1) ? g_srcc[pos + 1] : 0;
            for (; pos + 2 <= r1; pos += 2) {
                int srcA = sA, srcB = sB;
                sA = (pos + 2 < r1) ? g_srcc[pos + 2] : 0;
                sB = (pos + 3 < r1) ? g_srcc[pos + 3] : 0;
                float4 aleA = alec[pos];
                float4 aleB = alec[pos + 1];
                float4 sfA  = ((const float4*)g_als)[srcA];
                float4 sfB  = ((const float4*)g_als)[srcB];
                float4 xvA  = x4[(size_t)srcA * 32 + lane];
                float4 xvB  = x4[(size_t)srcB * 32 + lane];
                float aA[4] = {sfA.x + ad.x + aleA.x, sfA.y + ad.y + aleA.y,
                               sfA.z + ad.z + aleA.z, sfA.w + ad.w + aleA.w};
                float aB[4] = {sfB.x + ad.x + aleB.x, sfB.y + ad.y + aleB.y,
                               sfB.z + ad.z + aleB.z, sfB.w + ad.w + aleB.w};
                leaky_exp4(aA);
                leaky_exp4(aB);
                #pragma unroll
                for (int h = 0; h < 4; h++) z[h] += aA[h] + aB[h];
                #pragma unroll
                for (int h = 0; h < 4; h++) {
                    acc[h].x += aA[h] * xvA.x + aB[h] * xvB.x;
                    acc[h].y += aA[h] * xvA.y + aB[h] * xvB.y;
                    acc[h].z += aA[h] * xvA.z + aB[h] * xvB.z;
                    acc[h].w += aA[h] * xvA.w + aB[h] * xvB.w;
                }
            }
            if (pos < r1) {   // odd tail
                int srcA = sA;
                float4 aleA = alec[pos];
                float4 sfA  = ((const float4*)g_als)[srcA];
                float4 xvA  = x4[(size_t)srcA * 32 + lane];
                float aA[4] = {sfA.x + ad.x + aleA.x, sfA.y + ad.y + aleA.y,
                               sfA.z + ad.z + aleA.z, sfA.w + ad.w + aleA.w};
                leaky_exp4(aA);
                #pragma unroll
                for (int h = 0; h < 4; h++) z[h] += aA[h];
                #pragma unroll
                for (int h = 0; h < 4; h++) {
                    acc[h].x += aA[h] * xvA.x; acc[h].y += aA[h] * xvA.y;
                    acc[h].z += aA[h] * xvA.z; acc[h].w += aA[h] * xvA.w;
                }
            }
            #pragma unroll
            for (int h = 0; h < 4; h++) {
                float w = __fdividef(0.25f, z[h] + 1e-16f);
                ((float4*)ys)[m * (YS_STR / 4) + h * 32 + lane] =
                    make_float4(acc[h].x * w, acc[h].y * w, acc[h].z * w, acc[h].w * w);
            }
        } else {
            #pragma unroll
            for (int h = 0; h < 4; h++)
                ((float4*)ys)[m * (YS_STR / 4) + h * 32 + lane] = make_float4(0.f, 0.f, 0.f, 0.f);
        }
    }
    __syncthreads();

    // ---- phase 2: D = y @ W2 via tf32 mma, 3-pass hi/lo split ----
    {
        int r = lane >> 2, c = lane & 3;
        int nt0 = wid * 2;
        const float4* wf = (const float4*)(g_wfrag + (size_t)layer * WFRAG_PER_L);
        float d[2][2][4];
        #pragma unroll
        for (int i = 0; i < 2; i++)
            #pragma unroll
            for (int j = 0; j < 2; j++)
                #pragma unroll
                for (int q = 0; q < 4; q++) d[i][j][q] = 0.f;

        for (int kt = 0; kt < 64; kt++) {
            float4 bA = wf[(kt * 16 + nt0) * 32 + lane];
            float4 bB = wf[(kt * 16 + nt0 + 1) * 32 + lane];
            uint32_t bAh0 = __float_as_uint(bA.x), bAh1 = __float_as_uint(bA.y);
            uint32_t bAl0 = __float_as_uint(bA.z), bAl1 = __float_as_uint(bA.w);
            uint32_t bBh0 = __float_as_uint(bB.x), bBh1 = __float_as_uint(bB.y);
            uint32_t bBl0 = __float_as_uint(bB.z), bBl1 = __float_as_uint(bB.w);
            #pragma unroll
            for (int mt = 0; mt < 2; mt++) {
                int base = (mt * 16 + r) * YS_STR + kt * 8 + c;
                float a0 = ys[base];
                float a1 = ys[base + 8 * YS_STR];
                float a2 = ys[base + 4];
                float a3 = ys[base + 8 * YS_STR + 4];
                uint32_t h0 = f2tf32(a0), h1 = f2tf32(a1), h2 = f2tf32(a2), h3 = f2tf32(a3);
                uint32_t l0 = __float_as_uint(a0 - __uint_as_float(h0));
                uint32_t l1 = __float_as_uint(a1 - __uint_as_float(h1));
                uint32_t l2 = __float_as_uint(a2 - __uint_as_float(h2));
                uint32_t l3 = __float_as_uint(a3 - __uint_as_float(h3));
                mma_tf32(d[mt][0], h0, h1, h2, h3, bAh0, bAh1);
                mma_tf32(d[mt][0], l0, l1, l2, l3, bAh0, bAh1);
                mma_tf32(d[mt][0], h0, h1, h2, h3, bAl0, bAl1);
                mma_tf32(d[mt][1], h0, h1, h2, h3, bBh0, bBh1);
                mma_tf32(d[mt][1], l0, l1, l2, l3, bBh0, bBh1);
                mma_tf32(d[mt][1], h0, h1, h2, h3, bBl0, bBl1);
            }
        }
        __syncthreads();   // all warps done reading ys; safe to overwrite as LN buffer

        // epilogue: + bias + residual; stage into ys with LN_STR
        #pragma unroll
        for (int mt = 0; mt < 2; mt++) {
            #pragma unroll
            for (int j = 0; j < 2; j++) {
                int col = (nt0 + j) * 8 + c * 2;
                int rl  = mt * 16 + r;
                int grow = n0 + rl;
                float bj0 = bias[col], bj1 = bias[col + 1];
                float v0 = d[mt][j][0] + bj0 + xin[(size_t)grow * Hh + col];
                float v1 = d[mt][j][1] + bj1 + xin[(size_t)grow * Hh + col + 1];
                float v2 = d[mt][j][2] + bj0 + xin[(size_t)(grow + 8) * Hh + col];
                float v3 = d[mt][j][3] + bj1 + xin[(size_t)(grow + 8) * Hh + col + 1];
                ys[rl * LN_STR + col]           = v0;
                ys[rl * LN_STR + col + 1]       = v1;
                ys[(rl + 8) * LN_STR + col]     = v2;
                ys[(rl + 8) * LN_STR + col + 1] = v3;
            }
        }
    }
    __syncthreads();

    // ---- phase 3: LN + GELU, 8 warps x 4 rows ----
    float4 gg = ((const float4*)lg)[lane];
    float4 bb = ((const float4*)lb)[lane];
    #pragma unroll
    for (int mm = 0; mm < 4; mm++) {
        int m = wid * 4 + mm;
        int row = n0 + m;
        float v[4] = {ys[m * LN_STR + lane * 4],     ys[m * LN_STR + lane * 4 + 1],
                      ys[m * LN_STR + lane * 4 + 2], ys[m * LN_STR + lane * 4 + 3]};
        float sum = v[0] + v[1] + v[2] + v[3];
        #pragma unroll
        for (int o = 16; o > 0; o >>= 1) sum += __shfl_xor_sync(0xffffffffu, sum, o);
        float mu = sum * (1.0f / Hh);
        float sq = 0.f;
        #pragma unroll
        for (int i = 0; i < 4; i++) { float t = v[i] - mu; sq += t * t; }
        #pragma unroll
        for (int o = 16; o > 0; o >>= 1) sq += __shfl_xor_sync(0xffffffffu, sq, o);
        float inv = rsqrtf(sq * (1.0f / Hh) + 1e-5f);
        float gv[4] = {gg.x, gg.y, gg.z, gg.w};
        float bv[4] = {bb.x, bb.y, bb.z, bb.w};
        #pragma unroll
        for (int i = 0; i < 4; i++) {
            float y = (v[i] - mu) * inv * gv[i] + bv[i];
            y = 0.5f * y * (1.0f + erff(y * 0.70710678118654752f));
            v[i] = y;
        }
        float4 ov = make_float4(v[0], v[1], v[2], v[3]);
        ((float4*)xout)[(size_t)row * 32 + lane] = ov;
        if (last && row < Nn) ((float4*)dout)[(size_t)row * 32 + lane] = ov;
    }
}

// ------------------- K11: pooling atomics -------------------
__global__ void k_pool(const float* __restrict__ x,
                       const int* __restrict__ batch, const int* __restrict__ types) {
    int n = blockIdx.x * 8 + (threadIdx.x >> 5);
    if (n >= Nn) return;
    int lane = threadIdx.x & 31;
    int b = batch[n];
    int t = types[n];
    int r = (t <= 5) ? 0 : ((t <= 20) ? 1 : 2);
    if (lane == 0) atomicAdd(&g_cnt[b], 1.0f);
    #pragma unroll
    for (int i = 0; i < 4; i++) {
        int c = lane + 32 * i;
        float v = x[(size_t)n * Hh + c];
        atomicAdd(&g_pool[(b * 4 + r) * Hh + c], v);
        atomicAdd(&g_pool[(b * 4 + 3) * Hh + c], v);
    }
}

// ------------------- K12: divide & write embedding -------------------
__global__ void k_emb(float* __restrict__ dout) {
    int idx = blockIdx.x * blockDim.x + threadIdx.x;
    if (idx >= Bb * 4 * Hh) return;
    int b = idx / (4 * Hh);
    float c = fmaxf(g_cnt[b], 1.0f);
    dout[(size_t)Nn * Hh + idx] = g_pool[idx] / c;
}

// ------------------- host -------------------
extern "C" void kernel_launch(void* const* d_in, const int* in_sizes, int n_in,
                              void* d_out, int out_size) {
    const float* nf   = (const float*)d_in[0];
    const float* ef   = (const float*)d_in[1];
    const int*   types= (const int*)d_in[2];
    const int*   ei   = (const int*)d_in[3];
    const int*   batch= (const int*)d_in[4];
    const float* Wp   = (const float*)d_in[5];
    const float* bp   = (const float*)d_in[6];
    const float* tt   = (const float*)d_in[7];
    const float* Wep  = (const float*)d_in[8];
    const float* bep  = (const float*)d_in[9];
    const float* Wg   = (const float*)d_in[10];
    const float* Weg  = (const float*)d_in[11];
    const float* as_  = (const float*)d_in[12];
    const float* ad_  = (const float*)d_in[13];
    const float* ae_  = (const float*)d_in[14];
    const float* gb   = (const float*)d_in[15];
    const float* lng  = (const float*)d_in[16];
    const float* lnb  = (const float*)d_in[17];
    float* dout = (float*)d_out;

    const int SMEM_LAYER = 32 * YS_STR * 4;   // 66048 B

    static int smem_set = 0;
    if (!smem_set) {
        cudaFuncSetAttribute(k_layer, cudaFuncAttributeMaxDynamicSharedMemorySize, SMEM_LAYER);
        smem_set = 1;
    }

    void *p_efsum, *p_deg, *p_off, *p_pool, *p_cnt, *p_xA, *p_xB;
    cudaGetSymbolAddress(&p_efsum, g_efsum);
    cudaGetSymbolAddress(&p_deg,  g_deg);
    cudaGetSymbolAddress(&p_off,  g_off);
    cudaGetSymbolAddress(&p_pool, g_pool);
    cudaGetSymbolAddress(&p_cnt,  g_cnt);
    cudaGetSymbolAddress(&p_xA,   g_xA);
    cudaGetSymbolAddress(&p_xB,   g_xB);

    cudaMemsetAsync(p_efsum, 0, FEd * sizeof(float));
    cudaMemsetAsync(p_deg,  0, Nn * sizeof(int));
    cudaMemsetAsync(p_off,  0, Nn * sizeof(int));

    k_padzero<<<(32 * Hh + 255) / 256, 256>>>();
    k_hist<<<(Ee + 255) / 256, 256>>>(ei);
    k_scan<<<1, 1024>>>();
    k_fill<<<(Ee + 255) / 256, 256>>>(ei);

    k_proj_tables<<<(3 * Ll * Hh * HEADS + 255) / 256, 256>>>(Wg, Weg, as_, ad_, ae_);
    k_aep2<<<(Ll * HEADS * FEd + Ll * HEADS + 127) / 128, 128>>>(Wep, bep);
    k_wfrag<<<(Ll * 64 * 16 * 32 + 255) / 256, 256>>>(Wg);
    k_nodeproj<<<Nn / 16, 128>>>(nf, Wp, bp, tt, types);
    k_efsum<<<512, 256>>>(ef);
    k_loop_ale2<<<1, 32>>>();
    k_ale_eorder<<<(Ee + 7) / 8, 256>>>(ef);

    float* xA = (float*)p_xA;
    float* xB = (float*)p_xB;
    for (int l = 0; l < Ll; l++) {
        const float* xin = (l & 1) ? xB : xA;
        float* xout      = (l & 1) ? xA : xB;
        k_att_sd<<<(Nn + 7) / 8, 256>>>(l, xin);
        k_layer<<<(Nn + 31) / 32, 256, SMEM_LAYER>>>(l, xin, xout,
                                                     gb + l * Hh, lng + l * Hh, lnb + l * Hh,
                                                     dout, l == Ll - 1);
    }

    const float* xfinal = (Ll & 1) ? xB : xA;   // L=3 -> final in xB
    cudaMemsetAsync(p_pool, 0, Bb * 4 * Hh * sizeof(float));
    cudaMemsetAsync(p_cnt,  0, Bb * sizeof(float));
    k_pool<<<(Nn + 7) / 8, 256>>>(xfinal, batch, types);
    k_emb<<<(Bb * 4 * Hh + 255) / 256, 256>>>(dout);
}